// round 14
// baseline (speedup 1.0000x reference)
#include <cuda_runtime.h>
#include <cuda_fp16.h>
#include <cstdint>

// ===========================================================================
// AxialAttention: ONE persistent DAG-scheduled kernel runs fp32->fp16
// conversion AND all 5 GEMMs (mma.sync fp16 m16n8k16 + ldmatrix, 3-stage
// cp.async, 2 CTAs/SM). Global queue of 1856 items, dependency-gated via
// counters. Softmax fused into GEMM epilogues.
//   items 0..63     : convert X (32 blocks) / W (32 blocks), interleaved
//   items 64..575   : QK  = Xh@[Wq;Wk]^T + [bq;bk]   [4096,2048] fp16
//   items 576..831  : Vth = Wvh@Xh^T+bv              [1024,4096] fp16
//   items 832..1343 : P   = exp(Q@K^T/128) unnorm fp16 + rowsum atomics
//   items 1344..1599: Yh  = (P@Vt^T)/rowsum, shuffle-stored
//   items 1600..1855: out = Yh@Woh^T + bo (fp32)
// ===========================================================================

#define BK 64
#define ROW_BYTES 128
#define STG_BYTES (128 * ROW_BYTES)   // 16 KB
#define STAGES 3
#define SMEM_TOT (2 * STAGES * STG_BYTES)  // 96 KB -> 2 CTAs/SM
#define N_ITEMS 1856

// scratch
__device__ __half g_Xh[4096 * 1024];
__device__ __half g_Wh[4 * 1024 * 1024];
__device__ float  g_bqk[2048];
__device__ __half g_QK[4096 * 2048];
__device__ __half g_Vt[1024 * 4096];
__device__ __half g_P [2ll * 2048 * 2048];
__device__ __half g_Y [4096 * 1024];
__device__ float  g_rsum[2 * 2048];
// [0]=qhead [1..32]=cQK [33..40]=cVt [41..72]=cS [73..88]=cPV [89..120]=cX [121..152]=cW
__device__ int    g_sync[192];

__device__ __forceinline__ void mma_f16(float* d, const uint32_t* a,
                                        uint32_t b0, uint32_t b1) {
    asm volatile(
        "mma.sync.aligned.m16n8k16.row.col.f32.f16.f16.f32 "
        "{%0,%1,%2,%3}, {%4,%5,%6,%7}, {%8,%9}, {%0,%1,%2,%3};"
        : "+f"(d[0]), "+f"(d[1]), "+f"(d[2]), "+f"(d[3])
        : "r"(a[0]), "r"(a[1]), "r"(a[2]), "r"(a[3]), "r"(b0), "r"(b1));
}
__device__ __forceinline__ void ldsm4(uint32_t* r, uint32_t addr) {
    asm volatile("ldmatrix.sync.aligned.m8n8.x4.shared.b16 {%0,%1,%2,%3}, [%4];"
        : "=r"(r[0]), "=r"(r[1]), "=r"(r[2]), "=r"(r[3]) : "r"(addr));
}

#define CP_ASYNC(dst, src) \
    asm volatile("cp.async.cg.shared.global [%0], [%1], 16;" :: "r"(dst), \
                 "l"(__cvta_generic_to_global(src)))
#define CP_COMMIT() asm volatile("cp.async.commit_group;" ::: "memory")
#define CP_WAIT1()  asm volatile("cp.async.wait_group 1;" ::: "memory")

__device__ __forceinline__ void waitcnt(int* c, int need) {
    if (threadIdx.x == 0) {
        while (atomicAdd(c, 0) < need) __nanosleep(128);
        __threadfence();
    }
    __syncthreads();
}
__device__ __forceinline__ void donecnt(int* c) {
    __threadfence();
    __syncthreads();
    if (threadIdx.x == 0) atomicAdd(c, 1);
}

// ---------------------------------------------------------------------------
// GEMM body (saturated mainloop): 128x128 tile, 8 warps, 3 stages.
// MODE 0: plain store, bias by column.   MODE 1: plain store, bias by row.
// MODE 2: shuffle store (reference reshape), scaled by 1/rowsum[row].
// MODE 3: exp() store (unnormalized softmax), accumulate rowsum atomically.
// ---------------------------------------------------------------------------
template <int MODE, bool HALF_OUT>
__device__ __forceinline__ void gemm_body(
    const __half* __restrict__ A, int lda, long long sA,
    const __half* __restrict__ B, int ldb, long long sB,
    const float* __restrict__ bias, float* __restrict__ rowsum,
    void* __restrict__ Cv, int ldC, long long sC,
    int nch, float alpha, int bx, int by, int bz)
{
    extern __shared__ __align__(128) char smc[];

    const __half* Ab = A + bz * sA + (long long)by * 128 * lda;
    const __half* Bb = B + bz * sB + (long long)bx * 128 * ldb;

    int tid = threadIdx.x, lane = tid & 31, wid = tid >> 5;
    int gr = lane >> 2, qc = lane & 3;
    int mw = (wid >> 2) * 64, nw = (wid & 3) * 32;

    uint32_t sA32 = (uint32_t)__cvta_generic_to_shared(smc);
    uint32_t sB32 = sA32 + STAGES * STG_BYTES;

    int t8 = lane & 7, half8 = (lane >> 3) & 1, cg = lane >> 4;
    uint32_t aRow[4], aX7[4], bRow[2], bX7[2];
#pragma unroll
    for (int mf = 0; mf < 4; mf++) {
        int r = mw + mf * 16 + half8 * 8 + t8;
        aRow[mf] = (uint32_t)r * ROW_BYTES;
        aX7[mf] = (uint32_t)(r & 7);
    }
#pragma unroll
    for (int p = 0; p < 2; p++) {
        int r = nw + p * 16 + half8 * 8 + t8;
        bRow[p] = (uint32_t)r * ROW_BYTES;
        bX7[p] = (uint32_t)(r & 7);
    }

    int lr = tid >> 3;
    int lc = tid & 7;

    float acc[4][4][4];
#pragma unroll
    for (int i = 0; i < 4; i++)
#pragma unroll
        for (int j = 0; j < 4; j++)
#pragma unroll
            for (int t = 0; t < 4; t++) acc[i][j][t] = 0.f;

    auto load_stage = [&](int ch, int st) {
        long long ko = (long long)ch * BK + lc * 8;
#pragma unroll
        for (int it = 0; it < 4; it++) {
            int r = it * 32 + lr;
            uint32_t so = (uint32_t)(st * STG_BYTES + r * ROW_BYTES +
                                     ((lc ^ (r & 7)) << 4));
            CP_ASYNC(sA32 + so, Ab + (long long)r * lda + ko);
            CP_ASYNC(sB32 + so, Bb + (long long)r * ldb + ko);
        }
    };

    load_stage(0, 0);
    CP_COMMIT();
    load_stage(1, 1);
    CP_COMMIT();

    int st = 0;
    for (int ch = 0; ch < nch; ch++) {
        CP_WAIT1();
        __syncthreads();
        if (ch + 2 < nch) load_stage(ch + 2, (ch + 2) % STAGES);
        CP_COMMIT();

        uint32_t stA = sA32 + st * STG_BYTES;
        uint32_t stB = sB32 + st * STG_BYTES;
        if (++st == STAGES) st = 0;
#pragma unroll
        for (int ks = 0; ks < 4; ks++) {
            uint32_t c = (uint32_t)(ks * 2 + cg);
            uint32_t af[4][4], bb[2][4];
#pragma unroll
            for (int mf = 0; mf < 4; mf++)
                ldsm4(af[mf], stA + aRow[mf] + ((c ^ aX7[mf]) << 4));
#pragma unroll
            for (int p = 0; p < 2; p++)
                ldsm4(bb[p], stB + bRow[p] + ((c ^ bX7[p]) << 4));
#pragma unroll
            for (int mf = 0; mf < 4; mf++)
#pragma unroll
                for (int nf = 0; nf < 4; nf++)
                    mma_f16(acc[mf][nf], af[mf],
                            bb[nf >> 1][nf & 1], bb[nf >> 1][2 + (nf & 1)]);
        }
    }

    // epilogue
#pragma unroll
    for (int mf = 0; mf < 4; mf++) {
        int row = by * 128 + mw + mf * 16 + gr;
        float sum0 = 0.f, sum1 = 0.f;
        float inv0 = 1.f, inv1 = 1.f;
        if (MODE == 2) {
            const float* rs = rowsum + bz * 2048;
            inv0 = 1.0f / rs[row];
            inv1 = 1.0f / rs[row + 8];
        }
#pragma unroll
        for (int nf = 0; nf < 4; nf++) {
            int col = bx * 128 + nw + nf * 8 + 2 * qc;
            float v0 = acc[mf][nf][0] * alpha;
            float v1 = acc[mf][nf][1] * alpha;
            float v2 = acc[mf][nf][2] * alpha;
            float v3 = acc[mf][nf][3] * alpha;
            if (MODE == 0 && bias) {
                float b0 = bias[col], b1 = bias[col + 1];
                v0 += b0; v1 += b1; v2 += b0; v3 += b1;
            }
            if (MODE == 1) {
                float b0 = bias[row], b1 = bias[row + 8];
                v0 += b0; v1 += b0; v2 += b1; v3 += b1;
            }
            if (MODE == 2) {
                v0 *= inv0; v1 *= inv0; v2 *= inv1; v3 *= inv1;
            }
            if (MODE == 3) {
                v0 = __expf(v0); v1 = __expf(v1);
                v2 = __expf(v2); v3 = __expf(v3);
                sum0 += v0 + v1; sum1 += v2 + v3;
            }
            long long o0, o1;
            if (MODE == 2) {
                int h = col >> 6, d0 = col & 63;
                o0 = (long long)(h * 128 + (row >> 4)) * 1024 + ((row & 15) << 6) + d0;
                int row2 = row + 8;
                o1 = (long long)(h * 128 + (row2 >> 4)) * 1024 + ((row2 & 15) << 6) + d0;
            } else {
                o0 = (long long)row * ldC + col;
                o1 = o0 + 8ll * ldC;
            }
            if (HALF_OUT) {
                __half* Cb = (__half*)Cv + bz * sC;
                *(__half2*)(Cb + o0) = __floats2half2_rn(v0, v1);
                *(__half2*)(Cb + o1) = __floats2half2_rn(v2, v3);
            } else {
                float* Cb = (float*)Cv + bz * sC;
                *(float2*)(Cb + o0) = make_float2(v0, v1);
                *(float2*)(Cb + o1) = make_float2(v2, v3);
            }
        }
        if (MODE == 3) {
            sum0 += __shfl_xor_sync(0xffffffffu, sum0, 1);
            sum0 += __shfl_xor_sync(0xffffffffu, sum0, 2);
            sum1 += __shfl_xor_sync(0xffffffffu, sum1, 1);
            sum1 += __shfl_xor_sync(0xffffffffu, sum1, 2);
            if (qc == 0) {
                float* rs = rowsum + bz * 2048;
                atomicAdd(rs + row, sum0);
                atomicAdd(rs + row + 8, sum1);
            }
        }
    }
}

// convert one 128-row block (131072 floats) fp32 -> fp16
__device__ __forceinline__ void convert_block(const float4* __restrict__ src,
                                              __half* __restrict__ dst)
{
    int tid = threadIdx.x;
#pragma unroll 4
    for (int i = tid; i < 32768; i += 256) {
        float4 v = src[i];
        __half2 h0 = __floats2half2_rn(v.x, v.y);
        __half2 h1 = __floats2half2_rn(v.z, v.w);
        *(uint2*)(dst + (long long)i * 4) =
            make_uint2(*(uint32_t*)&h0, *(uint32_t*)&h1);
    }
}

// ---------------------------------------------------------------------------
// persistent DAG kernel
// ---------------------------------------------------------------------------
__global__ void __launch_bounds__(256, 2) mega(
    const float4* __restrict__ xf,
    const float4* __restrict__ w0, const float4* __restrict__ w1,
    const float4* __restrict__ w2, const float4* __restrict__ w3,
    __half* __restrict__ Xh, __half* __restrict__ Wh,
    const float* __restrict__ bqk, const float* __restrict__ bv,
    const float* __restrict__ bo,
    __half* __restrict__ QK, __half* __restrict__ Vt,
    __half* __restrict__ P, __half* __restrict__ Y,
    float* __restrict__ rsum, int* __restrict__ sync,
    float* __restrict__ out)
{
    __shared__ int s_item;
    int* qhead = sync;
    int* cQK = sync + 1;      // [32] x16
    int* cVt = sync + 33;     // [8]  x32
    int* cS  = sync + 41;     // [32] x16
    int* cPV = sync + 73;     // [16] x16
    int* cX  = sync + 89;     // [32] x1
    int* cW  = sync + 121;    // [32] x1

    for (;;) {
        __syncthreads();
        if (threadIdx.x == 0) s_item = atomicAdd(qhead, 1);
        __syncthreads();
        int it = s_item;
        if (it >= N_ITEMS) return;

        if (it < 64) {
            // conversion items, X/W interleaved
            int b = it >> 1;
            if ((it & 1) == 0) {
                convert_block(xf + (long long)b * 32768, Xh + (long long)b * 131072);
                donecnt(&cX[b]);
            } else {
                const float4* ws[4] = {w0, w1, w2, w3};
                convert_block(ws[b >> 3] + (long long)(b & 7) * 32768,
                              Wh + (long long)b * 131072);
                donecnt(&cW[b]);
            }
        } else if (it < 576) {
            // QK = Xh @ [Wq;Wk]^T + bqk : gx=16, gy=32
            int i1 = it - 64;
            int bx = i1 & 15, by = i1 >> 4;
            waitcnt(&cX[by], 1);
            waitcnt(&cW[bx], 1);
            gemm_body<0, true>(Xh, 1024, 0, Wh, 1024, 0, bqk, nullptr,
                               QK, 2048, 0, 16, 1.f, bx, by, 0);
            donecnt(&cQK[by]);
        } else if (it < 832) {
            // Vt = Wv @ Xh^T + bv : gx=32, gy=8   (Wv = W blocks 16..23)
            int i2 = it - 576;
            int bx = i2 & 31, by = i2 >> 5;
            waitcnt(&cW[16 + by], 1);
            waitcnt(&cX[bx], 1);
            gemm_body<1, true>(Wh + 2097152, 1024, 0, Xh, 1024, 0, bv, nullptr,
                               Vt, 4096, 0, 16, 1.f, bx, by, 0);
            donecnt(&cVt[by]);
        } else if (it < 1344) {
            // P = exp(Q @ K^T / 128) : gx=16, gy=16, z=2
            int i3 = it - 832;
            int z = i3 >> 8, r = i3 & 255, by = r >> 4, bx = r & 15;
            waitcnt(&cQK[z * 16 + by], 16);
            waitcnt(&cQK[z * 16 + bx], 16);
            gemm_body<3, true>(QK, 2048, 2048ll * 2048, QK + 1024, 2048, 2048ll * 2048,
                               nullptr, rsum, P, 2048, 2048ll * 2048,
                               16, 1.f / 128.f, bx, by, z);
            donecnt(&cS[z * 16 + by]);
        } else if (it < 1600) {
            // Y = (P @ Vt^T)/rowsum shuffled : gx=8, gy=16, z=2
            int i4 = it - 1344;
            int z = i4 >> 7, r = i4 & 127, bx = r >> 4, by = r & 15;
            waitcnt(&cS[z * 16 + by], 16);
            waitcnt(&cVt[bx], 32);
            gemm_body<2, true>(P, 2048, 2048ll * 2048, Vt, 4096, 2048,
                               nullptr, rsum, Y, 1024, 2048ll * 1024,
                               32, 1.f, bx, by, z);
            donecnt(&cPV[z * 8 + bx]);
        } else {
            // out = Y @ Wo^T + bo : gx=8, gy=32   (Wo = W blocks 24..31)
            int i5 = it - 1600;
            int by = i5 >> 3, bx = i5 & 7;
            int z = by >> 4, h = by & 15;
            waitcnt(&cW[24 + bx], 1);
            waitcnt(&cPV[z * 8 + (h >> 1)], 16);
            gemm_body<0, false>(Y, 1024, 0, Wh + 3145728, 1024, 0, bo, nullptr,
                                out, 1024, 0, 16, 1.f, bx, by, 0);
        }
    }
}

// ---------------------------------------------------------------------------
// tiny init: bias concat + rowsum/sync zero
// ---------------------------------------------------------------------------
__global__ __launch_bounds__(256) void init_k(
    const float* __restrict__ bq, const float* __restrict__ bk,
    float* __restrict__ bqk, float* __restrict__ rsum, int* __restrict__ sync)
{
    int i = blockIdx.x * 256 + threadIdx.x;
    if (i < 2048) bqk[i] = (i < 1024) ? bq[i] : bk[i - 1024];
    if (i < 4096) rsum[i] = 0.f;
    if (i < 192)  sync[i] = 0;
}

// ---------------------------------------------------------------------------
extern "C" void kernel_launch(void* const* d_in, const int* in_sizes, int n_in,
                              void* d_out, int out_size)
{
    const float* x  = (const float*)d_in[0];
    const float* bq = (const float*)d_in[2];
    const float* bk = (const float*)d_in[4];
    const float* bv = (const float*)d_in[6];
    const float* bo = (const float*)d_in[8];
    float* out = (float*)d_out;

    __half *Xh, *Wh, *QK, *Vt, *P, *Y;
    float *bqk, *rsum;
    int *sync;
    cudaGetSymbolAddress((void**)&Xh,   g_Xh);
    cudaGetSymbolAddress((void**)&Wh,   g_Wh);
    cudaGetSymbolAddress((void**)&QK,   g_QK);
    cudaGetSymbolAddress((void**)&Vt,   g_Vt);
    cudaGetSymbolAddress((void**)&P,    g_P);
    cudaGetSymbolAddress((void**)&Y,    g_Y);
    cudaGetSymbolAddress((void**)&bqk,  g_bqk);
    cudaGetSymbolAddress((void**)&rsum, g_rsum);
    cudaGetSymbolAddress((void**)&sync, g_sync);

    int NSM = 148;
    cudaDeviceGetAttribute(&NSM, cudaDevAttrMultiProcessorCount, 0);

    cudaFuncSetAttribute(mega, cudaFuncAttributeMaxDynamicSharedMemorySize, SMEM_TOT);

    init_k<<<16, 256>>>(bq, bk, bqk, rsum, sync);

    mega<<<2 * NSM, 256, SMEM_TOT>>>(
        (const float4*)x,
        (const float4*)d_in[1], (const float4*)d_in[3],
        (const float4*)d_in[5], (const float4*)d_in[7],
        Xh, Wh, bqk, bv, bo, QK, Vt, P, Y, rsum, sync, out);
}

// round 15
// speedup vs baseline: 1.1704x; 1.1704x over previous
#include <cuda_runtime.h>
#include <cuda_fp16.h>
#include <cstdint>

// ===========================================================================
// AxialAttention: ONE persistent DAG-scheduled kernel (R13 structure) with
// FINE-GRAINED fp32->fp16 conversion items (256 sub-items, ~0.125MB each --
// R14's failure was 64 coarse latency-bound items).
// mma.sync fp16 m16n8k16 + ldmatrix, 3-stage cp.async, 2 CTAs/SM.
//   items 0..255    : convert X/W sub-blocks (4 sub-items per 128-row block)
//   items 256..767  : QK  = Xh@[Wq;Wk]^T + [bq;bk]   [4096,2048] fp16
//   items 768..1023 : Vth = Wvh@Xh^T+bv              [1024,4096] fp16
//   items 1024..1535: P   = exp(Q@K^T/128) unnorm fp16 + rowsum atomics
//   items 1536..1791: Yh  = (P@Vt^T)/rowsum, shuffle-stored
//   items 1792..2047: out = Yh@Woh^T + bo (fp32)
// ===========================================================================

#define BK 64
#define ROW_BYTES 128
#define STG_BYTES (128 * ROW_BYTES)   // 16 KB
#define STAGES 3
#define SMEM_TOT (2 * STAGES * STG_BYTES)  // 96 KB -> 2 CTAs/SM
#define N_ITEMS 2048

// scratch
__device__ __half g_Xh[4096 * 1024];
__device__ __half g_Wh[4 * 1024 * 1024];
__device__ float  g_bqk[2048];
__device__ __half g_QK[4096 * 2048];
__device__ __half g_Vt[1024 * 4096];
__device__ __half g_P [2ll * 2048 * 2048];
__device__ __half g_Y [4096 * 1024];
__device__ float  g_rsum[2 * 2048];
// [0]=qhead [1..32]=cQK(x16) [33..40]=cVt(x32) [41..72]=cS(x16)
// [73..88]=cPV(x16) [89..120]=cX(x4) [121..152]=cW(x4)
__device__ int    g_sync[192];

__device__ __forceinline__ void mma_f16(float* d, const uint32_t* a,
                                        uint32_t b0, uint32_t b1) {
    asm volatile(
        "mma.sync.aligned.m16n8k16.row.col.f32.f16.f16.f32 "
        "{%0,%1,%2,%3}, {%4,%5,%6,%7}, {%8,%9}, {%0,%1,%2,%3};"
        : "+f"(d[0]), "+f"(d[1]), "+f"(d[2]), "+f"(d[3])
        : "r"(a[0]), "r"(a[1]), "r"(a[2]), "r"(a[3]), "r"(b0), "r"(b1));
}
__device__ __forceinline__ void ldsm4(uint32_t* r, uint32_t addr) {
    asm volatile("ldmatrix.sync.aligned.m8n8.x4.shared.b16 {%0,%1,%2,%3}, [%4];"
        : "=r"(r[0]), "=r"(r[1]), "=r"(r[2]), "=r"(r[3]) : "r"(addr));
}

#define CP_ASYNC(dst, src) \
    asm volatile("cp.async.cg.shared.global [%0], [%1], 16;" :: "r"(dst), \
                 "l"(__cvta_generic_to_global(src)))
#define CP_COMMIT() asm volatile("cp.async.commit_group;" ::: "memory")
#define CP_WAIT1()  asm volatile("cp.async.wait_group 1;" ::: "memory")

__device__ __forceinline__ void waitcnt(int* c, int need) {
    if (threadIdx.x == 0) {
        while (atomicAdd(c, 0) < need) __nanosleep(128);
        __threadfence();
    }
    __syncthreads();
}
__device__ __forceinline__ void donecnt(int* c) {
    __threadfence();
    __syncthreads();
    if (threadIdx.x == 0) atomicAdd(c, 1);
}

// ---------------------------------------------------------------------------
// GEMM body (saturated mainloop): 128x128 tile, 8 warps, 3 stages.
// MODE 0: plain store, bias by column.   MODE 1: plain store, bias by row.
// MODE 2: shuffle store (reference reshape), scaled by 1/rowsum[row].
// MODE 3: exp() store (unnormalized softmax), accumulate rowsum atomically.
// ---------------------------------------------------------------------------
template <int MODE, bool HALF_OUT>
__device__ __forceinline__ void gemm_body(
    const __half* __restrict__ A, int lda, long long sA,
    const __half* __restrict__ B, int ldb, long long sB,
    const float* __restrict__ bias, float* __restrict__ rowsum,
    void* __restrict__ Cv, int ldC, long long sC,
    int nch, float alpha, int bx, int by, int bz)
{
    extern __shared__ __align__(128) char smc[];

    const __half* Ab = A + bz * sA + (long long)by * 128 * lda;
    const __half* Bb = B + bz * sB + (long long)bx * 128 * ldb;

    int tid = threadIdx.x, lane = tid & 31, wid = tid >> 5;
    int gr = lane >> 2, qc = lane & 3;
    int mw = (wid >> 2) * 64, nw = (wid & 3) * 32;

    uint32_t sA32 = (uint32_t)__cvta_generic_to_shared(smc);
    uint32_t sB32 = sA32 + STAGES * STG_BYTES;

    int t8 = lane & 7, half8 = (lane >> 3) & 1, cg = lane >> 4;
    uint32_t aRow[4], aX7[4], bRow[2], bX7[2];
#pragma unroll
    for (int mf = 0; mf < 4; mf++) {
        int r = mw + mf * 16 + half8 * 8 + t8;
        aRow[mf] = (uint32_t)r * ROW_BYTES;
        aX7[mf] = (uint32_t)(r & 7);
    }
#pragma unroll
    for (int p = 0; p < 2; p++) {
        int r = nw + p * 16 + half8 * 8 + t8;
        bRow[p] = (uint32_t)r * ROW_BYTES;
        bX7[p] = (uint32_t)(r & 7);
    }

    int lr = tid >> 3;
    int lc = tid & 7;

    float acc[4][4][4];
#pragma unroll
    for (int i = 0; i < 4; i++)
#pragma unroll
        for (int j = 0; j < 4; j++)
#pragma unroll
            for (int t = 0; t < 4; t++) acc[i][j][t] = 0.f;

    auto load_stage = [&](int ch, int st) {
        long long ko = (long long)ch * BK + lc * 8;
#pragma unroll
        for (int it = 0; it < 4; it++) {
            int r = it * 32 + lr;
            uint32_t so = (uint32_t)(st * STG_BYTES + r * ROW_BYTES +
                                     ((lc ^ (r & 7)) << 4));
            CP_ASYNC(sA32 + so, Ab + (long long)r * lda + ko);
            CP_ASYNC(sB32 + so, Bb + (long long)r * ldb + ko);
        }
    };

    load_stage(0, 0);
    CP_COMMIT();
    load_stage(1, 1);
    CP_COMMIT();

    int st = 0;
    for (int ch = 0; ch < nch; ch++) {
        CP_WAIT1();
        __syncthreads();
        if (ch + 2 < nch) load_stage(ch + 2, (ch + 2) % STAGES);
        CP_COMMIT();

        uint32_t stA = sA32 + st * STG_BYTES;
        uint32_t stB = sB32 + st * STG_BYTES;
        if (++st == STAGES) st = 0;
#pragma unroll
        for (int ks = 0; ks < 4; ks++) {
            uint32_t c = (uint32_t)(ks * 2 + cg);
            uint32_t af[4][4], bb[2][4];
#pragma unroll
            for (int mf = 0; mf < 4; mf++)
                ldsm4(af[mf], stA + aRow[mf] + ((c ^ aX7[mf]) << 4));
#pragma unroll
            for (int p = 0; p < 2; p++)
                ldsm4(bb[p], stB + bRow[p] + ((c ^ bX7[p]) << 4));
#pragma unroll
            for (int mf = 0; mf < 4; mf++)
#pragma unroll
                for (int nf = 0; nf < 4; nf++)
                    mma_f16(acc[mf][nf], af[mf],
                            bb[nf >> 1][nf & 1], bb[nf >> 1][2 + (nf & 1)]);
        }
    }

    // epilogue
#pragma unroll
    for (int mf = 0; mf < 4; mf++) {
        int row = by * 128 + mw + mf * 16 + gr;
        float sum0 = 0.f, sum1 = 0.f;
        float inv0 = 1.f, inv1 = 1.f;
        if (MODE == 2) {
            const float* rs = rowsum + bz * 2048;
            inv0 = 1.0f / rs[row];
            inv1 = 1.0f / rs[row + 8];
        }
#pragma unroll
        for (int nf = 0; nf < 4; nf++) {
            int col = bx * 128 + nw + nf * 8 + 2 * qc;
            float v0 = acc[mf][nf][0] * alpha;
            float v1 = acc[mf][nf][1] * alpha;
            float v2 = acc[mf][nf][2] * alpha;
            float v3 = acc[mf][nf][3] * alpha;
            if (MODE == 0 && bias) {
                float b0 = bias[col], b1 = bias[col + 1];
                v0 += b0; v1 += b1; v2 += b0; v3 += b1;
            }
            if (MODE == 1) {
                float b0 = bias[row], b1 = bias[row + 8];
                v0 += b0; v1 += b0; v2 += b1; v3 += b1;
            }
            if (MODE == 2) {
                v0 *= inv0; v1 *= inv0; v2 *= inv1; v3 *= inv1;
            }
            if (MODE == 3) {
                v0 = __expf(v0); v1 = __expf(v1);
                v2 = __expf(v2); v3 = __expf(v3);
                sum0 += v0 + v1; sum1 += v2 + v3;
            }
            long long o0, o1;
            if (MODE == 2) {
                int h = col >> 6, d0 = col & 63;
                o0 = (long long)(h * 128 + (row >> 4)) * 1024 + ((row & 15) << 6) + d0;
                int row2 = row + 8;
                o1 = (long long)(h * 128 + (row2 >> 4)) * 1024 + ((row2 & 15) << 6) + d0;
            } else {
                o0 = (long long)row * ldC + col;
                o1 = o0 + 8ll * ldC;
            }
            if (HALF_OUT) {
                __half* Cb = (__half*)Cv + bz * sC;
                *(__half2*)(Cb + o0) = __floats2half2_rn(v0, v1);
                *(__half2*)(Cb + o1) = __floats2half2_rn(v2, v3);
            } else {
                float* Cb = (float*)Cv + bz * sC;
                *(float2*)(Cb + o0) = make_float2(v0, v1);
                *(float2*)(Cb + o1) = make_float2(v2, v3);
            }
        }
        if (MODE == 3) {
            sum0 += __shfl_xor_sync(0xffffffffu, sum0, 1);
            sum0 += __shfl_xor_sync(0xffffffffu, sum0, 2);
            sum1 += __shfl_xor_sync(0xffffffffu, sum1, 1);
            sum1 += __shfl_xor_sync(0xffffffffu, sum1, 2);
            if (qc == 0) {
                float* rs = rowsum + bz * 2048;
                atomicAdd(rs + row, sum0);
                atomicAdd(rs + row + 8, sum1);
            }
        }
    }
}

// convert one sub-block: 8192 float4 (0.125 MB fp32) -> fp16
__device__ __forceinline__ void convert_sub(const float4* __restrict__ src,
                                            __half* __restrict__ dst)
{
    int tid = threadIdx.x;
#pragma unroll 8
    for (int i = tid; i < 8192; i += 256) {
        float4 v = src[i];
        __half2 h0 = __floats2half2_rn(v.x, v.y);
        __half2 h1 = __floats2half2_rn(v.z, v.w);
        *(uint2*)(dst + (long long)i * 4) =
            make_uint2(*(uint32_t*)&h0, *(uint32_t*)&h1);
    }
}

// ---------------------------------------------------------------------------
// persistent DAG kernel
// ---------------------------------------------------------------------------
__global__ void __launch_bounds__(256, 2) mega(
    const float4* __restrict__ xf,
    const float4* __restrict__ w0, const float4* __restrict__ w1,
    const float4* __restrict__ w2, const float4* __restrict__ w3,
    __half* __restrict__ Xh, __half* __restrict__ Wh,
    const float* __restrict__ bqk, const float* __restrict__ bv,
    const float* __restrict__ bo,
    __half* __restrict__ QK, __half* __restrict__ Vt,
    __half* __restrict__ P, __half* __restrict__ Y,
    float* __restrict__ rsum, int* __restrict__ sync,
    float* __restrict__ out)
{
    __shared__ int s_item;
    int* qhead = sync;
    int* cQK = sync + 1;      // [32] x16
    int* cVt = sync + 33;     // [8]  x32
    int* cS  = sync + 41;     // [32] x16
    int* cPV = sync + 73;     // [16] x16
    int* cX  = sync + 89;     // [32] x4
    int* cW  = sync + 121;    // [32] x4

    for (;;) {
        __syncthreads();
        if (threadIdx.x == 0) s_item = atomicAdd(qhead, 1);
        __syncthreads();
        int it = s_item;
        if (it >= N_ITEMS) return;

        if (it < 256) {
            // conversion sub-items: k = it; block b = k>>3, sub s = (k>>1)&3,
            // type = k&1 (0=X, 1=W). Block b's 8 sub-items are items 8b..8b+7.
            int b = it >> 3, s = (it >> 1) & 3;
            long long off4 = (long long)b * 32768 + (long long)s * 8192;
            long long offh = (long long)b * 131072 + (long long)s * 32768;
            if ((it & 1) == 0) {
                convert_sub(xf + off4, Xh + offh);
                donecnt(&cX[b]);
            } else {
                const float4* ws[4] = {w0, w1, w2, w3};
                convert_sub(ws[b >> 3] + (long long)(b & 7) * 32768 +
                            (long long)s * 8192, Wh + offh);
                donecnt(&cW[b]);
            }
        } else if (it < 768) {
            // QK = Xh @ [Wq;Wk]^T + bqk : gx=16, gy=32
            int i1 = it - 256;
            int bx = i1 & 15, by = i1 >> 4;
            waitcnt(&cX[by], 4);
            waitcnt(&cW[bx], 4);
            gemm_body<0, true>(Xh, 1024, 0, Wh, 1024, 0, bqk, nullptr,
                               QK, 2048, 0, 16, 1.f, bx, by, 0);
            donecnt(&cQK[by]);
        } else if (it < 1024) {
            // Vt = Wv @ Xh^T + bv : gx=32, gy=8   (Wv = W blocks 16..23)
            int i2 = it - 768;
            int bx = i2 & 31, by = i2 >> 5;
            waitcnt(&cW[16 + by], 4);
            waitcnt(&cX[bx], 4);
            gemm_body<1, true>(Wh + 2097152, 1024, 0, Xh, 1024, 0, bv, nullptr,
                               Vt, 4096, 0, 16, 1.f, bx, by, 0);
            donecnt(&cVt[by]);
        } else if (it < 1536) {
            // P = exp(Q @ K^T / 128) : gx=16, gy=16, z=2
            int i3 = it - 1024;
            int z = i3 >> 8, r = i3 & 255, by = r >> 4, bx = r & 15;
            waitcnt(&cQK[z * 16 + by], 16);
            waitcnt(&cQK[z * 16 + bx], 16);
            gemm_body<3, true>(QK, 2048, 2048ll * 2048, QK + 1024, 2048, 2048ll * 2048,
                               nullptr, rsum, P, 2048, 2048ll * 2048,
                               16, 1.f / 128.f, bx, by, z);
            donecnt(&cS[z * 16 + by]);
        } else if (it < 1792) {
            // Y = (P @ Vt^T)/rowsum shuffled : gx=8, gy=16, z=2
            int i4 = it - 1536;
            int z = i4 >> 7, r = i4 & 127, bx = r >> 4, by = r & 15;
            waitcnt(&cS[z * 16 + by], 16);
            waitcnt(&cVt[bx], 32);
            gemm_body<2, true>(P, 2048, 2048ll * 2048, Vt, 4096, 2048,
                               nullptr, rsum, Y, 1024, 2048ll * 1024,
                               32, 1.f, bx, by, z);
            donecnt(&cPV[z * 8 + bx]);
        } else {
            // out = Y @ Wo^T + bo : gx=8, gy=32   (Wo = W blocks 24..31)
            int i5 = it - 1792;
            int by = i5 >> 3, bx = i5 & 7;
            int z = by >> 4, h = by & 15;
            waitcnt(&cW[24 + bx], 4);
            waitcnt(&cPV[z * 8 + (h >> 1)], 16);
            gemm_body<0, false>(Y, 1024, 0, Wh + 3145728, 1024, 0, bo, nullptr,
                                out, 1024, 0, 16, 1.f, bx, by, 0);
        }
    }
}

// ---------------------------------------------------------------------------
// tiny init: bias concat + rowsum/sync zero
// ---------------------------------------------------------------------------
__global__ __launch_bounds__(256) void init_k(
    const float* __restrict__ bq, const float* __restrict__ bk,
    float* __restrict__ bqk, float* __restrict__ rsum, int* __restrict__ sync)
{
    int i = blockIdx.x * 256 + threadIdx.x;
    if (i < 2048) bqk[i] = (i < 1024) ? bq[i] : bk[i - 1024];
    if (i < 4096) rsum[i] = 0.f;
    if (i < 192)  sync[i] = 0;
}

// ---------------------------------------------------------------------------
extern "C" void kernel_launch(void* const* d_in, const int* in_sizes, int n_in,
                              void* d_out, int out_size)
{
    const float* x  = (const float*)d_in[0];
    const float* bq = (const float*)d_in[2];
    const float* bk = (const float*)d_in[4];
    const float* bv = (const float*)d_in[6];
    const float* bo = (const float*)d_in[8];
    float* out = (float*)d_out;

    __half *Xh, *Wh, *QK, *Vt, *P, *Y;
    float *bqk, *rsum;
    int *sync;
    cudaGetSymbolAddress((void**)&Xh,   g_Xh);
    cudaGetSymbolAddress((void**)&Wh,   g_Wh);
    cudaGetSymbolAddress((void**)&QK,   g_QK);
    cudaGetSymbolAddress((void**)&Vt,   g_Vt);
    cudaGetSymbolAddress((void**)&P,    g_P);
    cudaGetSymbolAddress((void**)&Y,    g_Y);
    cudaGetSymbolAddress((void**)&bqk,  g_bqk);
    cudaGetSymbolAddress((void**)&rsum, g_rsum);
    cudaGetSymbolAddress((void**)&sync, g_sync);

    int NSM = 148;
    cudaDeviceGetAttribute(&NSM, cudaDevAttrMultiProcessorCount, 0);

    cudaFuncSetAttribute(mega, cudaFuncAttributeMaxDynamicSharedMemorySize, SMEM_TOT);

    init_k<<<16, 256>>>(bq, bk, bqk, rsum, sync);

    mega<<<2 * NSM, 256, SMEM_TOT>>>(
        (const float4*)x,
        (const float4*)d_in[1], (const float4*)d_in[3],
        (const float4*)d_in[5], (const float4*)d_in[7],
        Xh, Wh, bqk, bv, bo, QK, Vt, P, Y, rsum, sync, out);
}

// round 16
// speedup vs baseline: 1.2991x; 1.1100x over previous
#include <cuda_runtime.h>
#include <cuda_fp16.h>
#include <cstdint>

// ===========================================================================
// AxialAttention: separate f2h_all (8192 CTAs) + ONE persistent DAG kernel
// (R13 champion structure). New in R16: split Q-half/K-half QK counters and
// wavefront-ordered S items -> earlier S starts behind QK.
// mma.sync fp16 m16n8k16 + ldmatrix, 3-stage cp.async, 2 CTAs/SM.
//   items 0..511    : QK  = Xh@[Wq;Wk]^T + [bq;bk]   [4096,2048] fp16
//   items 512..767  : Vth = Wvh@Xh^T+bv              [1024,4096] fp16
//   items 768..1279 : P   = exp(Q@K^T/128) unnorm fp16 + rowsum atomics
//   items 1280..1535: Yh  = (P@Vt^T)/rowsum, shuffle-stored
//   items 1536..1791: out = Yh@Woh^T + bo (fp32)
// ===========================================================================

#define BK 64
#define ROW_BYTES 128
#define STG_BYTES (128 * ROW_BYTES)   // 16 KB
#define STAGES 3
#define SMEM_TOT (2 * STAGES * STG_BYTES)  // 96 KB -> 2 CTAs/SM
#define N_ITEMS 1792

// scratch
__device__ __half g_Xh[4096 * 1024];
__device__ __half g_Wh[4 * 1024 * 1024];
__device__ float  g_bqk[2048];
__device__ __half g_QK[4096 * 2048];
__device__ __half g_Vt[1024 * 4096];
__device__ __half g_P [2ll * 2048 * 2048];
__device__ __half g_Y [4096 * 1024];
__device__ float  g_rsum[2 * 2048];
// [0]=qhead [1..32]=cQKq(x8) [33..64]=cQKk(x8) [65..72]=cVt(x32)
// [73..104]=cS(x16) [105..120]=cPV(x16)
__device__ int    g_sync[192];

__device__ __forceinline__ void mma_f16(float* d, const uint32_t* a,
                                        uint32_t b0, uint32_t b1) {
    asm volatile(
        "mma.sync.aligned.m16n8k16.row.col.f32.f16.f16.f32 "
        "{%0,%1,%2,%3}, {%4,%5,%6,%7}, {%8,%9}, {%0,%1,%2,%3};"
        : "+f"(d[0]), "+f"(d[1]), "+f"(d[2]), "+f"(d[3])
        : "r"(a[0]), "r"(a[1]), "r"(a[2]), "r"(a[3]), "r"(b0), "r"(b1));
}
__device__ __forceinline__ void ldsm4(uint32_t* r, uint32_t addr) {
    asm volatile("ldmatrix.sync.aligned.m8n8.x4.shared.b16 {%0,%1,%2,%3}, [%4];"
        : "=r"(r[0]), "=r"(r[1]), "=r"(r[2]), "=r"(r[3]) : "r"(addr));
}

#define CP_ASYNC(dst, src) \
    asm volatile("cp.async.cg.shared.global [%0], [%1], 16;" :: "r"(dst), \
                 "l"(__cvta_generic_to_global(src)))
#define CP_COMMIT() asm volatile("cp.async.commit_group;" ::: "memory")
#define CP_WAIT1()  asm volatile("cp.async.wait_group 1;" ::: "memory")

__device__ __forceinline__ void waitcnt(int* c, int need) {
    if (threadIdx.x == 0) {
        while (atomicAdd(c, 0) < need) __nanosleep(128);
        __threadfence();
    }
    __syncthreads();
}
__device__ __forceinline__ void donecnt(int* c) {
    __threadfence();
    __syncthreads();
    if (threadIdx.x == 0) atomicAdd(c, 1);
}

// ---------------------------------------------------------------------------
// GEMM body (saturated mainloop): 128x128 tile, 8 warps, 3 stages.
// MODE 0: plain store, bias by column.   MODE 1: plain store, bias by row.
// MODE 2: shuffle store (reference reshape), scaled by 1/rowsum[row].
// MODE 3: exp() store (unnormalized softmax), accumulate rowsum atomically.
// ---------------------------------------------------------------------------
template <int MODE, bool HALF_OUT>
__device__ __forceinline__ void gemm_body(
    const __half* __restrict__ A, int lda, long long sA,
    const __half* __restrict__ B, int ldb, long long sB,
    const float* __restrict__ bias, float* __restrict__ rowsum,
    void* __restrict__ Cv, int ldC, long long sC,
    int nch, float alpha, int bx, int by, int bz)
{
    extern __shared__ __align__(128) char smc[];

    const __half* Ab = A + bz * sA + (long long)by * 128 * lda;
    const __half* Bb = B + bz * sB + (long long)bx * 128 * ldb;

    int tid = threadIdx.x, lane = tid & 31, wid = tid >> 5;
    int gr = lane >> 2, qc = lane & 3;
    int mw = (wid >> 2) * 64, nw = (wid & 3) * 32;

    uint32_t sA32 = (uint32_t)__cvta_generic_to_shared(smc);
    uint32_t sB32 = sA32 + STAGES * STG_BYTES;

    int t8 = lane & 7, half8 = (lane >> 3) & 1, cg = lane >> 4;
    uint32_t aRow[4], aX7[4], bRow[2], bX7[2];
#pragma unroll
    for (int mf = 0; mf < 4; mf++) {
        int r = mw + mf * 16 + half8 * 8 + t8;
        aRow[mf] = (uint32_t)r * ROW_BYTES;
        aX7[mf] = (uint32_t)(r & 7);
    }
#pragma unroll
    for (int p = 0; p < 2; p++) {
        int r = nw + p * 16 + half8 * 8 + t8;
        bRow[p] = (uint32_t)r * ROW_BYTES;
        bX7[p] = (uint32_t)(r & 7);
    }

    int lr = tid >> 3;
    int lc = tid & 7;

    float acc[4][4][4];
#pragma unroll
    for (int i = 0; i < 4; i++)
#pragma unroll
        for (int j = 0; j < 4; j++)
#pragma unroll
            for (int t = 0; t < 4; t++) acc[i][j][t] = 0.f;

    auto load_stage = [&](int ch, int st) {
        long long ko = (long long)ch * BK + lc * 8;
#pragma unroll
        for (int it = 0; it < 4; it++) {
            int r = it * 32 + lr;
            uint32_t so = (uint32_t)(st * STG_BYTES + r * ROW_BYTES +
                                     ((lc ^ (r & 7)) << 4));
            CP_ASYNC(sA32 + so, Ab + (long long)r * lda + ko);
            CP_ASYNC(sB32 + so, Bb + (long long)r * ldb + ko);
        }
    };

    load_stage(0, 0);
    CP_COMMIT();
    load_stage(1, 1);
    CP_COMMIT();

    int st = 0;
    for (int ch = 0; ch < nch; ch++) {
        CP_WAIT1();
        __syncthreads();
        if (ch + 2 < nch) load_stage(ch + 2, (ch + 2) % STAGES);
        CP_COMMIT();

        uint32_t stA = sA32 + st * STG_BYTES;
        uint32_t stB = sB32 + st * STG_BYTES;
        if (++st == STAGES) st = 0;
#pragma unroll
        for (int ks = 0; ks < 4; ks++) {
            uint32_t c = (uint32_t)(ks * 2 + cg);
            uint32_t af[4][4], bb[2][4];
#pragma unroll
            for (int mf = 0; mf < 4; mf++)
                ldsm4(af[mf], stA + aRow[mf] + ((c ^ aX7[mf]) << 4));
#pragma unroll
            for (int p = 0; p < 2; p++)
                ldsm4(bb[p], stB + bRow[p] + ((c ^ bX7[p]) << 4));
#pragma unroll
            for (int mf = 0; mf < 4; mf++)
#pragma unroll
                for (int nf = 0; nf < 4; nf++)
                    mma_f16(acc[mf][nf], af[mf],
                            bb[nf >> 1][nf & 1], bb[nf >> 1][2 + (nf & 1)]);
        }
    }

    // epilogue
#pragma unroll
    for (int mf = 0; mf < 4; mf++) {
        int row = by * 128 + mw + mf * 16 + gr;
        float sum0 = 0.f, sum1 = 0.f;
        float inv0 = 1.f, inv1 = 1.f;
        if (MODE == 2) {
            const float* rs = rowsum + bz * 2048;
            inv0 = 1.0f / rs[row];
            inv1 = 1.0f / rs[row + 8];
        }
#pragma unroll
        for (int nf = 0; nf < 4; nf++) {
            int col = bx * 128 + nw + nf * 8 + 2 * qc;
            float v0 = acc[mf][nf][0] * alpha;
            float v1 = acc[mf][nf][1] * alpha;
            float v2 = acc[mf][nf][2] * alpha;
            float v3 = acc[mf][nf][3] * alpha;
            if (MODE == 0 && bias) {
                float b0 = bias[col], b1 = bias[col + 1];
                v0 += b0; v1 += b1; v2 += b0; v3 += b1;
            }
            if (MODE == 1) {
                float b0 = bias[row], b1 = bias[row + 8];
                v0 += b0; v1 += b0; v2 += b1; v3 += b1;
            }
            if (MODE == 2) {
                v0 *= inv0; v1 *= inv0; v2 *= inv1; v3 *= inv1;
            }
            if (MODE == 3) {
                v0 = __expf(v0); v1 = __expf(v1);
                v2 = __expf(v2); v3 = __expf(v3);
                sum0 += v0 + v1; sum1 += v2 + v3;
            }
            long long o0, o1;
            if (MODE == 2) {
                int h = col >> 6, d0 = col & 63;
                o0 = (long long)(h * 128 + (row >> 4)) * 1024 + ((row & 15) << 6) + d0;
                int row2 = row + 8;
                o1 = (long long)(h * 128 + (row2 >> 4)) * 1024 + ((row2 & 15) << 6) + d0;
            } else {
                o0 = (long long)row * ldC + col;
                o1 = o0 + 8ll * ldC;
            }
            if (HALF_OUT) {
                __half* Cb = (__half*)Cv + bz * sC;
                *(__half2*)(Cb + o0) = __floats2half2_rn(v0, v1);
                *(__half2*)(Cb + o1) = __floats2half2_rn(v2, v3);
            } else {
                float* Cb = (float*)Cv + bz * sC;
                *(float2*)(Cb + o0) = make_float2(v0, v1);
                *(float2*)(Cb + o1) = make_float2(v2, v3);
            }
        }
        if (MODE == 3) {
            sum0 += __shfl_xor_sync(0xffffffffu, sum0, 1);
            sum0 += __shfl_xor_sync(0xffffffffu, sum0, 2);
            sum1 += __shfl_xor_sync(0xffffffffu, sum1, 1);
            sum1 += __shfl_xor_sync(0xffffffffu, sum1, 2);
            if (qc == 0) {
                float* rs = rowsum + bz * 2048;
                atomicAdd(rs + row, sum0);
                atomicAdd(rs + row + 8, sum1);
            }
        }
    }
}

// ---------------------------------------------------------------------------
// persistent DAG kernel: queue of 1792 tile-items, dependency-gated
// ---------------------------------------------------------------------------
__global__ void __launch_bounds__(256, 2) mega(
    const __half* __restrict__ Xh, const __half* __restrict__ Wh,
    const float* __restrict__ bqk, const float* __restrict__ bv,
    const float* __restrict__ bo,
    __half* __restrict__ QK, __half* __restrict__ Vt,
    __half* __restrict__ P, __half* __restrict__ Y,
    float* __restrict__ rsum, int* __restrict__ sync,
    float* __restrict__ out)
{
    __shared__ int s_item;
    int* qhead = sync;
    int* cQKq = sync + 1;      // [32] x8  (Q-half of each QK row)
    int* cQKk = sync + 33;     // [32] x8  (K-half)
    int* cVt  = sync + 65;     // [8]  x32
    int* cS   = sync + 73;     // [32] x16
    int* cPV  = sync + 105;    // [16] x16

    for (;;) {
        __syncthreads();
        if (threadIdx.x == 0) s_item = atomicAdd(qhead, 1);
        __syncthreads();
        int it = s_item;
        if (it >= N_ITEMS) return;

        if (it < 512) {
            // QK = Xh @ [Wq;Wk]^T + bqk : gx=16, gy=32
            int bx = it & 15, by = it >> 4;
            gemm_body<0, true>(Xh, 1024, 0, Wh, 1024, 0, bqk, nullptr,
                               QK, 2048, 0, 16, 1.f, bx, by, 0);
            donecnt(bx < 8 ? &cQKq[by] : &cQKk[by]);
        } else if (it < 768) {
            // Vt = Wv @ Xh^T + bv : gx=32, gy=8
            int i2 = it - 512;
            int bx = i2 & 31, by = i2 >> 5;
            gemm_body<1, true>(Wh + 2097152, 1024, 0, Xh, 1024, 0, bv, nullptr,
                               Vt, 4096, 0, 16, 1.f, bx, by, 0);
            donecnt(&cVt[by]);
        } else if (it < 1280) {
            // P = exp(Q @ K^T / 128) : gx=16, gy=16, z=2.
            // Wavefront order within each z: item r needs QK rows <= isqrt(r).
            int i3 = it - 768;
            int z = i3 >> 8, r = i3 & 255;
            int m = (int)sqrtf((float)r);
            while ((m + 1) * (m + 1) <= r) m++;
            while (m * m > r) m--;
            int k = r - m * m;
            int by, bx;
            if (k < m)            { by = m;     bx = k; }
            else if (k < 2 * m)   { by = k - m; bx = m; }
            else                  { by = m;     bx = m; }
            waitcnt(&cQKq[z * 16 + by], 8);   // Q-half of row by
            waitcnt(&cQKk[z * 16 + bx], 8);   // K-half of row bx
            gemm_body<3, true>(QK, 2048, 2048ll * 2048, QK + 1024, 2048, 2048ll * 2048,
                               nullptr, rsum, P, 2048, 2048ll * 2048,
                               16, 1.f / 128.f, bx, by, z);
            donecnt(&cS[z * 16 + by]);
        } else if (it < 1536) {
            // Y = (P @ Vt^T)/rowsum shuffled : gx=8, gy=16, z=2 (by fastest)
            int i4 = it - 1280;
            int z = i4 >> 7, r = i4 & 127, bx = r >> 4, by = r & 15;
            waitcnt(&cS[z * 16 + by], 16);
            waitcnt(&cVt[bx], 32);
            gemm_body<2, true>(P, 2048, 2048ll * 2048, Vt, 4096, 2048,
                               nullptr, rsum, Y, 1024, 2048ll * 1024,
                               32, 1.f, bx, by, z);
            donecnt(&cPV[z * 8 + bx]);
        } else {
            // out = Y @ Wo^T + bo : gx=8, gy=32 (by-major, matches PV order)
            int i5 = it - 1536;
            int by = i5 >> 3, bx = i5 & 7;
            int z = by >> 4, h = by & 15;
            waitcnt(&cPV[z * 8 + (h >> 1)], 16);
            gemm_body<0, false>(Y, 1024, 0, Wh + 3145728, 1024, 0, bo, nullptr,
                                out, 1024, 0, 16, 1.f, bx, by, 0);
        }
    }
}

// ---------------------------------------------------------------------------
// fused fp32->fp16 conversion + bias concat + rowsum/sync zeroing (8192 CTAs)
// ---------------------------------------------------------------------------
__global__ __launch_bounds__(256) void f2h_all(
    const float4* __restrict__ x,
    const float4* __restrict__ w0, const float4* __restrict__ w1,
    const float4* __restrict__ w2, const float4* __restrict__ w3,
    const float* __restrict__ bq, const float* __restrict__ bk,
    __half* __restrict__ Xh, __half* __restrict__ Wh,
    float* __restrict__ bqk, float* __restrict__ rsum, int* __restrict__ sync)
{
    int i = blockIdx.x * 256 + threadIdx.x;
    if (i < 2048) bqk[i] = (i < 1024) ? bq[i] : bk[i - 1024];
    if (i < 4096) rsum[i] = 0.f;
    if (i < 192)  sync[i] = 0;
    const float4* src;
    __half* dst;
    if (i < (1 << 20)) { src = x + i; dst = Xh + (long long)i * 4; }
    else {
        int j = i - (1 << 20);
        int w = j >> 18, off = j & ((1 << 18) - 1);
        const float4* ws[4] = {w0, w1, w2, w3};
        src = ws[w] + off;
        dst = Wh + ((long long)w << 20) + (long long)off * 4;
    }
    float4 v = *src;
    __half2 h0 = __floats2half2_rn(v.x, v.y);
    __half2 h1 = __floats2half2_rn(v.z, v.w);
    *(uint2*)dst = make_uint2(*(uint32_t*)&h0, *(uint32_t*)&h1);
}

// ---------------------------------------------------------------------------
extern "C" void kernel_launch(void* const* d_in, const int* in_sizes, int n_in,
                              void* d_out, int out_size)
{
    const float* x  = (const float*)d_in[0];
    const float* bq = (const float*)d_in[2];
    const float* bk = (const float*)d_in[4];
    const float* bv = (const float*)d_in[6];
    const float* bo = (const float*)d_in[8];
    float* out = (float*)d_out;

    __half *Xh, *Wh, *QK, *Vt, *P, *Y;
    float *bqk, *rsum;
    int *sync;
    cudaGetSymbolAddress((void**)&Xh,   g_Xh);
    cudaGetSymbolAddress((void**)&Wh,   g_Wh);
    cudaGetSymbolAddress((void**)&QK,   g_QK);
    cudaGetSymbolAddress((void**)&Vt,   g_Vt);
    cudaGetSymbolAddress((void**)&P,    g_P);
    cudaGetSymbolAddress((void**)&Y,    g_Y);
    cudaGetSymbolAddress((void**)&bqk,  g_bqk);
    cudaGetSymbolAddress((void**)&rsum, g_rsum);
    cudaGetSymbolAddress((void**)&sync, g_sync);

    int NSM = 148;
    cudaDeviceGetAttribute(&NSM, cudaDevAttrMultiProcessorCount, 0);

    cudaFuncSetAttribute(mega, cudaFuncAttributeMaxDynamicSharedMemorySize, SMEM_TOT);

    f2h_all<<<8192, 256>>>((const float4*)x,
                           (const float4*)d_in[1], (const float4*)d_in[3],
                           (const float4*)d_in[5], (const float4*)d_in[7],
                           bq, bk, Xh, Wh, bqk, rsum, sync);

    mega<<<2 * NSM, 256, SMEM_TOT>>>(Xh, Wh, bqk, bv, bo,
                                     QK, Vt, P, Y, rsum, sync, out);
}